// round 8
// baseline (speedup 1.0000x reference)
#include <cuda_runtime.h>
#include <cstdint>
#include <math.h>

// ---------------------------------------------------------------------------
// Problem dims
// ---------------------------------------------------------------------------
#define T_STEPS 8192
#define IN_DIM  109
#define H_DIM   1024
#define G_DIM   4096   // 4*H
#define NBLK    128    // persistent blocks (<=148 SMs, 1 CTA/SM -> co-resident)

// ---------------------------------------------------------------------------
// Scratch (static device allocations; no cudaMalloc allowed)
// ---------------------------------------------------------------------------
__device__ float g_xproj[(size_t)T_STEPS * G_DIM];   // reused for both layers
__device__ float g_h0[(size_t)T_STEPS * H_DIM];
__device__ float g_h1[(size_t)T_STEPS * H_DIM];
__device__ float g_hbuf[2][2 * H_DIM];               // [layer][parity*1024 + j]
__device__ int   g_flags[2 * NBLK];                  // [layer*128 + block]

// ---------------------------------------------------------------------------
// Memory-order helpers
// ---------------------------------------------------------------------------
__device__ __forceinline__ int ld_acq(const int* p) {
    int v;
    asm volatile("ld.acquire.gpu.b32 %0, [%1];" : "=r"(v) : "l"(p) : "memory");
    return v;
}
__device__ __forceinline__ void st_rel(int* p, int v) {
    asm volatile("st.release.gpu.b32 [%0], %1;" :: "l"(p), "r"(v) : "memory");
}
__device__ __forceinline__ void fence_ar() {
    asm volatile("fence.acq_rel.gpu;" ::: "memory");
}
__device__ __forceinline__ float4 ld_cv4(const float4* p) {
    float4 v;
    asm volatile("ld.global.cv.v4.f32 {%0,%1,%2,%3}, [%4];"
                 : "=f"(v.x), "=f"(v.y), "=f"(v.z), "=f"(v.w) : "l"(p) : "memory");
    return v;
}
__device__ __forceinline__ void st_cg(float* p, float v) {
    asm volatile("st.global.cg.f32 [%0], %1;" :: "l"(p), "f"(v) : "memory");
}
__device__ __forceinline__ float sigmoidf_(float x) {
    return 1.0f / (1.0f + expf(-x));   // PRECISE (R1-proven)
}

// ---------------------------------------------------------------------------
// Init: zero flags + hbuf (every launch; graph replays reuse statics)
// ---------------------------------------------------------------------------
__global__ void init_kernel() {
    int i = blockIdx.x * blockDim.x + threadIdx.x;
    if (i < 2 * NBLK) g_flags[i] = 0;
    if (i < 2 * 2 * H_DIM) ((float*)g_hbuf)[i] = 0.0f;
}

// ---------------------------------------------------------------------------
// GEMM tile body: C[m0..+128][n0..+128] = A@B^T + bias1 + bias2 (R1-proven math)
// ---------------------------------------------------------------------------
__device__ void gemm_tile_body(
    const float* A, const float* B,
    const float* bias1, const float* bias2,
    float* C, int N, int K, int m0, int n0)
{
    __shared__ float As[8][132];
    __shared__ float Bs[8][132];

    const int tid = threadIdx.x;
    const int lr  = tid >> 1;
    const int lk4 = (tid & 1) * 4;
    const int ty  = tid >> 4;
    const int tx  = tid & 15;

    float acc[8][8];
#pragma unroll
    for (int i = 0; i < 8; i++)
#pragma unroll
        for (int j = 0; j < 8; j++) acc[i][j] = 0.0f;

    for (int k0 = 0; k0 < K; k0 += 8) {
#pragma unroll
        for (int e = 0; e < 4; e++) {
            int k = k0 + lk4 + e;
            float av = 0.0f, bv = 0.0f;
            if (k < K) {
                av = A[(size_t)(m0 + lr) * K + k];
                bv = B[(size_t)(n0 + lr) * K + k];
            }
            As[lk4 + e][lr] = av;
            Bs[lk4 + e][lr] = bv;
        }
        __syncthreads();
#pragma unroll
        for (int kk = 0; kk < 8; kk++) {
            float a[8], b[8];
            float4 a0 = *(const float4*)&As[kk][ty * 8];
            float4 a1 = *(const float4*)&As[kk][ty * 8 + 4];
            float4 b0 = *(const float4*)&Bs[kk][tx * 8];
            float4 b1 = *(const float4*)&Bs[kk][tx * 8 + 4];
            a[0]=a0.x; a[1]=a0.y; a[2]=a0.z; a[3]=a0.w;
            a[4]=a1.x; a[5]=a1.y; a[6]=a1.z; a[7]=a1.w;
            b[0]=b0.x; b[1]=b0.y; b[2]=b0.z; b[3]=b0.w;
            b[4]=b1.x; b[5]=b1.y; b[6]=b1.z; b[7]=b1.w;
#pragma unroll
            for (int i = 0; i < 8; i++)
#pragma unroll
                for (int j = 0; j < 8; j++)
                    acc[i][j] = fmaf(a[i], b[j], acc[i][j]);
        }
        __syncthreads();
    }

#pragma unroll
    for (int i = 0; i < 8; i++) {
        size_t row = (size_t)(m0 + ty * 8 + i) * N;
#pragma unroll
        for (int j = 0; j < 8; j++) {
            int n = n0 + tx * 8 + j;
            C[row + n] = acc[i][j] + bias1[n] + bias2[n];
        }
    }
}

// Standalone GEMM kernel (used for x_proj0; K=109)
__global__ __launch_bounds__(256) void gemm_nt_bias(
    const float* __restrict__ A, const float* __restrict__ B,
    const float* __restrict__ bias1, const float* __restrict__ bias2,
    float* __restrict__ C, int N, int K)
{
    gemm_tile_body(A, B, bias1, bias2, C, N, K, blockIdx.y * 128, blockIdx.x * 128);
}

// ---------------------------------------------------------------------------
// LSTM recurrence body (one layer). R1 numerics exactly; R7 tail; NEW:
// per-producer flag->data pairing (thread tid polls flags[tid>>1], the block
// producing the h elements it stages), cheaper release fence, final flag bump
// to T_STEPS+1 publishing the last h_all rows to gated consumer blocks.
// ---------------------------------------------------------------------------
__device__ void lstm_body(
    const float* __restrict__ Whh,   // [4096][1024]
    const float* xp,                 // [8192][4096] (may alias GEMM output)
    float* h_all,                    // [8192][1024]
    float* hbuf,                     // [2*1024]
    int* flags)                      // [128]
{
    const int b   = blockIdx.x;
    const int tid = threadIdx.x;
    const int rg  = tid >> 6;        // gate 0..3 (i,f,g,o)
    const int cg  = tid & 63;        // 0..63
    const int lane = tid & 31;
    const int warp = tid >> 5;
    const int half = warp & 1;

    __shared__ float4 hs4[256];
    __shared__ float  red[4][2][8];
    __shared__ float  actbuf[32];

    // Weights into registers (R1 layout).
    float w[8][16];
#pragma unroll
    for (int i = 0; i < 8; i++) {
        const float* wr = Whh + (size_t)(rg * 1024 + b * 8 + i) * 1024 + cg * 4;
#pragma unroll
        for (int q = 0; q < 4; q++) {
            float4 t4 = *(const float4*)(wr + q * 256);
            w[i][q * 4 + 0] = t4.x; w[i][q * 4 + 1] = t4.y;
            w[i][q * 4 + 2] = t4.z; w[i][q * 4 + 3] = t4.w;
        }
    }

    float c_state = 0.0f;   // meaningful for tid < 8

    for (int t = 0; t < T_STEPS; ++t) {
        // x_proj prefetch: warp 0, lane (4*jj+g) -> gate g of element jj.
        float xv = 0.0f;
        if (tid < 32)
            xv = __ldcs(xp + (size_t)t * G_DIM + (tid & 3) * H_DIM + b * 8 + (tid >> 2));

        // Acquire + fetch, paired per producer: thread tid stages h elements
        // [4*tid, 4*tid+4), produced by block (tid>>1). Poll exactly that flag,
        // then immediately load the data it guards (direct acquire->read).
        float4 hv;
        if (t > 0) {
            const int* fp = &flags[tid >> 1];
            int v = ld_acq(fp);
            if (v < t) {
                v = ld_acq(fp);               // immediate retry (near-ready case)
                while (v < t) { __nanosleep(64); v = ld_acq(fp); }
            }
            hv = ld_cv4((const float4*)(hbuf + ((t + 1) & 1) * H_DIM) + tid);
        } else {
            hv = make_float4(0.f, 0.f, 0.f, 0.f);
        }
        hs4[tid] = hv;
        __syncthreads();

        // Mat-vec partials: 8 rows x 16 cols per thread (R1 order).
        float acc[8];
#pragma unroll
        for (int i = 0; i < 8; i++) acc[i] = 0.0f;
        float4 hq[4];
#pragma unroll
        for (int q = 0; q < 4; q++) hq[q] = hs4[cg + q * 64];
#pragma unroll
        for (int i = 0; i < 8; i++) {
#pragma unroll
            for (int q = 0; q < 4; q++) {
                acc[i] = fmaf(w[i][q * 4 + 0], hq[q].x, acc[i]);
                acc[i] = fmaf(w[i][q * 4 + 1], hq[q].y, acc[i]);
                acc[i] = fmaf(w[i][q * 4 + 2], hq[q].z, acc[i]);
                acc[i] = fmaf(w[i][q * 4 + 3], hq[q].w, acc[i]);
            }
        }
#pragma unroll
        for (int i = 0; i < 8; i++) {
#pragma unroll
            for (int off = 16; off > 0; off >>= 1)
                acc[i] += __shfl_xor_sync(0xFFFFFFFFu, acc[i], off);
        }
        if (lane == 0) {
#pragma unroll
            for (int i = 0; i < 8; i++) red[rg][half][i] = acc[i];
        }
        __syncthreads();

        // Tail (R7-proven): warp 0 computes the 32 activations in parallel,
        // threads 0..7 combine with exact R1 expressions.
        if (tid < 32) {
            const int jj = tid >> 2;
            const int g  = tid & 3;
            float pre = red[g][0][jj] + red[g][1][jj] + xv;
            actbuf[tid] = (g == 2) ? tanhf(pre) : sigmoidf_(pre);
            __syncwarp(0xFFFFFFFFu);

            if (tid < 8) {
                float ig = actbuf[tid * 4 + 0];
                float fg = actbuf[tid * 4 + 1];
                float gg = actbuf[tid * 4 + 2];
                float og = actbuf[tid * 4 + 3];
                c_state = fg * c_state + ig * gg;
                float h  = og * tanhf(c_state);
                hbuf[(t & 1) * H_DIM + b * 8 + tid] = h;
                __syncwarp(0x000000FFu);
                if (tid == 0) {
                    fence_ar();                 // cumulative release fence (cheaper than fence.sc)
                    st_rel(&flags[b], t + 1);
                }
                __syncwarp(0x000000FFu);
                st_cg(h_all + (size_t)t * H_DIM + b * 8 + tid, h);
            }
        }
    }

    // Final bump: publish the last h_all rows (stores issued after the last
    // release) to gated consumer blocks. flags[b] -> T_STEPS+1.
    __syncthreads();
    if (tid == 0) {
        fence_ar();
        st_rel(&flags[b], T_STEPS + 1);
    }
}

// ---------------------------------------------------------------------------
// Fused kernel A: blocks 0..127 run layer-0 recurrence; blocks 128..2175 run
// gated GEMM1 tiles (xproj1 = h0 @ W_ih1^T + biases) into g_xproj.
// Gate flags0 >= m0+129 guarantees (a) h0 rows <= m0+127 visible and
// (b) xproj0 rows <= m0+128 already consumed -> overwrite is WAR-safe.
// ---------------------------------------------------------------------------
__global__ __launch_bounds__(256, 1) void fused_l0_gemm1(
    const float* __restrict__ Whh0,
    float* xproj,                    // g_xproj: L0 reads rows [t], GEMM writes rows behind frontier
    float* __restrict__ h0,
    float* hbuf, int* flags,
    const float* __restrict__ Wih1,
    const float* __restrict__ b_ih1, const float* __restrict__ b_hh1)
{
    if (blockIdx.x < NBLK) {
        lstm_body(Whh0, xproj, h0, hbuf, flags);
    } else {
        const int tile = blockIdx.x - NBLK;       // 0..2047
        const int n0 = (tile & 31) * 128;         // G_DIM/128 = 32
        const int m0 = (tile >> 5) * 128;         // T_STEPS/128 = 64
        const int gate = m0 + 129;                // <= 8193 = final bump
        if (threadIdx.x < NBLK) {
            while (ld_acq(&flags[threadIdx.x]) < gate) { __nanosleep(2048); }
        }
        __syncthreads();
        gemm_tile_body(h0, Wih1, b_ih1, b_hh1, xproj, G_DIM, H_DIM, m0, n0);
    }
}

// ---------------------------------------------------------------------------
// FC (109 outputs) + log_softmax body. 8 timesteps per block.
// ---------------------------------------------------------------------------
__device__ void fc_body(
    const float* __restrict__ H, const float* __restrict__ Wf,
    const float* __restrict__ bf, float* __restrict__ out, int t0)
{
    __shared__ float ws[IN_DIM][68];
    __shared__ float hsm[8][68];
    __shared__ float lg[8][112];

    const int tid = threadIdx.x;
    const int tt  = tid & 7;
    const int n4  = tid >> 3;

    float acc[4] = {0.f, 0.f, 0.f, 0.f};

    for (int kc = 0; kc < H_DIM; kc += 64) {
        for (int idx = tid; idx < IN_DIM * 16; idx += 256) {
            int n = idx >> 4, k4 = idx & 15;
            *(float4*)&ws[n][k4 * 4] = *(const float4*)&Wf[(size_t)n * H_DIM + kc + k4 * 4];
        }
        for (int idx = tid; idx < 8 * 16; idx += 256) {
            int r = idx >> 4, k4 = idx & 15;
            *(float4*)&hsm[r][k4 * 4] = *(const float4*)&H[(size_t)(t0 + r) * H_DIM + kc + k4 * 4];
        }
        __syncthreads();
#pragma unroll
        for (int k4 = 0; k4 < 16; k4++) {
            float4 hv = *(const float4*)&hsm[tt][k4 * 4];
#pragma unroll
            for (int i = 0; i < 4; i++) {
                int n = n4 + i * 32;
                if (n < IN_DIM) {
                    float4 wv = *(const float4*)&ws[n][k4 * 4];
                    acc[i] += hv.x * wv.x + hv.y * wv.y + hv.z * wv.z + hv.w * wv.w;
                }
            }
        }
        __syncthreads();
    }

#pragma unroll
    for (int i = 0; i < 4; i++) {
        int n = n4 + i * 32;
        if (n < IN_DIM) lg[tt][n] = acc[i] + bf[n];
    }
    __syncthreads();

    const int wp = tid >> 5, lane = tid & 31;
    {
        int t = wp;
        float v0 = (lane       < IN_DIM) ? lg[t][lane]       : -INFINITY;
        float v1 = (lane + 32  < IN_DIM) ? lg[t][lane + 32]  : -INFINITY;
        float v2 = (lane + 64  < IN_DIM) ? lg[t][lane + 64]  : -INFINITY;
        float v3 = (lane + 96  < IN_DIM) ? lg[t][lane + 96]  : -INFINITY;
        float mx = fmaxf(fmaxf(v0, v1), fmaxf(v2, v3));
#pragma unroll
        for (int o = 16; o > 0; o >>= 1) mx = fmaxf(mx, __shfl_xor_sync(0xFFFFFFFFu, mx, o));
        float se = expf(v0 - mx) + expf(v1 - mx) + expf(v2 - mx) + expf(v3 - mx);
#pragma unroll
        for (int o = 16; o > 0; o >>= 1) se += __shfl_xor_sync(0xFFFFFFFFu, se, o);
        float ls = mx + logf(se);
        size_t row = (size_t)(t0 + t) * IN_DIM;
        if (lane      < IN_DIM) out[row + lane]      = v0 - ls;
        if (lane + 32 < IN_DIM) out[row + lane + 32] = v1 - ls;
        if (lane + 64 < IN_DIM) out[row + lane + 64] = v2 - ls;
        if (lane + 96 < IN_DIM) out[row + lane + 96] = v3 - ls;
    }
}

// ---------------------------------------------------------------------------
// Fused kernel B: blocks 0..127 run layer-1 recurrence; blocks 128..1151 run
// gated FC+log_softmax tiles (h1 rows t0..t0+7 visible once flags1 >= t0+9).
// ---------------------------------------------------------------------------
__global__ __launch_bounds__(256, 1) void fused_l1_fc(
    const float* __restrict__ Whh1,
    const float* __restrict__ xproj,
    float* __restrict__ h1,
    float* hbuf, int* flags,
    const float* __restrict__ fc_w, const float* __restrict__ fc_b,
    float* __restrict__ out)
{
    if (blockIdx.x < NBLK) {
        lstm_body(Whh1, xproj, h1, hbuf, flags);
    } else {
        const int t0 = (blockIdx.x - NBLK) * 8;
        const int gate = t0 + 9;                  // <= 8193 = final bump
        if (threadIdx.x < NBLK) {
            while (ld_acq(&flags[threadIdx.x]) < gate) { __nanosleep(2048); }
        }
        __syncthreads();
        fc_body(h1, fc_w, fc_b, out, t0);
    }
}

// ---------------------------------------------------------------------------
// Launch
// ---------------------------------------------------------------------------
extern "C" void kernel_launch(void* const* d_in, const int* in_sizes, int n_in,
                              void* d_out, int out_size)
{
    const float* input  = (const float*)d_in[0];   // [8192,109]
    const float* W_ih0  = (const float*)d_in[1];   // [4096,109]
    const float* W_hh0  = (const float*)d_in[2];   // [4096,1024]
    const float* b_ih0  = (const float*)d_in[3];
    const float* b_hh0  = (const float*)d_in[4];
    const float* W_ih1  = (const float*)d_in[5];   // [4096,1024]
    const float* W_hh1  = (const float*)d_in[6];   // [4096,1024]
    const float* b_ih1  = (const float*)d_in[7];
    const float* b_hh1  = (const float*)d_in[8];
    const float* fc_w   = (const float*)d_in[9];   // [109,1024]
    const float* fc_b   = (const float*)d_in[10];
    float* out = (float*)d_out;

    static float* p_xproj = nullptr;
    static float* p_h0 = nullptr;
    static float* p_h1 = nullptr;
    static float* p_hbuf = nullptr;
    static int*   p_flags = nullptr;
    if (!p_xproj) {
        cudaGetSymbolAddress((void**)&p_xproj, g_xproj);
        cudaGetSymbolAddress((void**)&p_h0,    g_h0);
        cudaGetSymbolAddress((void**)&p_h1,    g_h1);
        cudaGetSymbolAddress((void**)&p_hbuf,  g_hbuf);
        cudaGetSymbolAddress((void**)&p_flags, g_flags);
    }

    // 1) reset barrier flags + h ping-pong buffers
    init_kernel<<<17, 256>>>();

    // 2) x_proj0 = input @ W_ih0^T + b_ih0 + b_hh0  (K=109, fast)
    {
        dim3 grid(G_DIM / 128, T_STEPS / 128);
        gemm_nt_bias<<<grid, 256>>>(input, W_ih0, b_ih0, b_hh0,
                                    p_xproj, G_DIM, IN_DIM);
    }

    // 3) layer-0 recurrence + gated GEMM1 (xproj1) overlapped in one launch
    fused_l0_gemm1<<<NBLK + 2048, 256>>>(W_hh0, p_xproj, p_h0,
                                         p_hbuf + 0, p_flags + 0,
                                         W_ih1, b_ih1, b_hh1);

    // 4) layer-1 recurrence + gated FC/log_softmax overlapped in one launch
    fused_l1_fc<<<NBLK + T_STEPS / 8, 256>>>(W_hh1, p_xproj, p_h1,
                                             p_hbuf + 2 * H_DIM, p_flags + NBLK,
                                             fc_w, fc_b, out);
}

// round 9
// speedup vs baseline: 1.7476x; 1.7476x over previous
#include <cuda_runtime.h>
#include <cstdint>
#include <math.h>

// ---------------------------------------------------------------------------
// Problem dims
// ---------------------------------------------------------------------------
#define T_STEPS 8192
#define IN_DIM  109
#define H_DIM   1024
#define G_DIM   4096   // 4*H
#define NBLK    128    // persistent blocks (<=148 SMs, 1 CTA/SM -> co-resident)

// ---------------------------------------------------------------------------
// Scratch (static device allocations; no cudaMalloc allowed)
// ---------------------------------------------------------------------------
__device__ float g_xproj[(size_t)T_STEPS * G_DIM];   // reused for both layers
__device__ float g_h0[(size_t)T_STEPS * H_DIM];
__device__ float g_h1[(size_t)T_STEPS * H_DIM];
__device__ float g_hbuf[2][2 * H_DIM];               // [layer][parity*1024 + j]
// Cumulative step counters, one per layer, each on its own 128B line.
// Producer adds 1 at end of each step; value 128*t  <=>  all blocks done t-1.
__device__ unsigned g_ctr[64];                       // [0] layer0, [32] layer1

// ---------------------------------------------------------------------------
// Memory-order helpers
// ---------------------------------------------------------------------------
__device__ __forceinline__ unsigned ld_acq_u(const unsigned* p) {
    unsigned v;
    asm volatile("ld.acquire.gpu.b32 %0, [%1];" : "=r"(v) : "l"(p) : "memory");
    return v;
}
__device__ __forceinline__ void red_add_relaxed(unsigned* p, unsigned v) {
    asm volatile("red.relaxed.gpu.global.add.u32 [%0], %1;" :: "l"(p), "r"(v) : "memory");
}
__device__ __forceinline__ void fence_ar() {
    asm volatile("fence.acq_rel.gpu;" ::: "memory");
}
__device__ __forceinline__ float4 ld_cv4(const float4* p) {
    float4 v;
    asm volatile("ld.global.cv.v4.f32 {%0,%1,%2,%3}, [%4];"
                 : "=f"(v.x), "=f"(v.y), "=f"(v.z), "=f"(v.w) : "l"(p) : "memory");
    return v;
}
__device__ __forceinline__ void st_cg(float* p, float v) {
    asm volatile("st.global.cg.f32 [%0], %1;" :: "l"(p), "f"(v) : "memory");
}
__device__ __forceinline__ float sigmoidf_(float x) {
    return 1.0f / (1.0f + expf(-x));   // PRECISE (R1-proven)
}

// ---------------------------------------------------------------------------
// Init: zero counters + hbuf (every launch; graph replays reuse statics)
// ---------------------------------------------------------------------------
__global__ void init_kernel() {
    int i = blockIdx.x * blockDim.x + threadIdx.x;
    if (i < 64) g_ctr[i] = 0u;
    if (i < 2 * 2 * H_DIM) ((float*)g_hbuf)[i] = 0.0f;
}

// ---------------------------------------------------------------------------
// GEMM:  C[m][n] = sum_k A[m][k]*B[n][k] + bias1[n] + bias2[n]   (R1-proven)
// ---------------------------------------------------------------------------
__global__ __launch_bounds__(256) void gemm_nt_bias(
    const float* __restrict__ A, const float* __restrict__ B,
    const float* __restrict__ bias1, const float* __restrict__ bias2,
    float* __restrict__ C, int N, int K)
{
    __shared__ float As[8][132];
    __shared__ float Bs[8][132];

    const int m0 = blockIdx.y * 128;
    const int n0 = blockIdx.x * 128;
    const int tid = threadIdx.x;
    const int lr  = tid >> 1;
    const int lk4 = (tid & 1) * 4;
    const int ty  = tid >> 4;
    const int tx  = tid & 15;

    float acc[8][8];
#pragma unroll
    for (int i = 0; i < 8; i++)
#pragma unroll
        for (int j = 0; j < 8; j++) acc[i][j] = 0.0f;

    for (int k0 = 0; k0 < K; k0 += 8) {
#pragma unroll
        for (int e = 0; e < 4; e++) {
            int k = k0 + lk4 + e;
            float av = 0.0f, bv = 0.0f;
            if (k < K) {
                av = A[(size_t)(m0 + lr) * K + k];
                bv = B[(size_t)(n0 + lr) * K + k];
            }
            As[lk4 + e][lr] = av;
            Bs[lk4 + e][lr] = bv;
        }
        __syncthreads();
#pragma unroll
        for (int kk = 0; kk < 8; kk++) {
            float a[8], b[8];
            float4 a0 = *(const float4*)&As[kk][ty * 8];
            float4 a1 = *(const float4*)&As[kk][ty * 8 + 4];
            float4 b0 = *(const float4*)&Bs[kk][tx * 8];
            float4 b1 = *(const float4*)&Bs[kk][tx * 8 + 4];
            a[0]=a0.x; a[1]=a0.y; a[2]=a0.z; a[3]=a0.w;
            a[4]=a1.x; a[5]=a1.y; a[6]=a1.z; a[7]=a1.w;
            b[0]=b0.x; b[1]=b0.y; b[2]=b0.z; b[3]=b0.w;
            b[4]=b1.x; b[5]=b1.y; b[6]=b1.z; b[7]=b1.w;
#pragma unroll
            for (int i = 0; i < 8; i++)
#pragma unroll
                for (int j = 0; j < 8; j++)
                    acc[i][j] = fmaf(a[i], b[j], acc[i][j]);
        }
        __syncthreads();
    }

#pragma unroll
    for (int i = 0; i < 8; i++) {
        size_t row = (size_t)(m0 + ty * 8 + i) * N;
#pragma unroll
        for (int j = 0; j < 8; j++) {
            int n = n0 + tx * 8 + j;
            C[row + n] = acc[i][j] + bias1[n] + bias2[n];
        }
    }
}

// ---------------------------------------------------------------------------
// Persistent LSTM recurrence — R1 numerics (bit-exact trajectory), counter
// barrier: producers red.add a single cumulative counter (one L2 line);
// ONLY thread 0 of each block polls it. Eliminates the flag-line poll storm
// that dominated the step time in R1/R7/R8.
// ---------------------------------------------------------------------------
__global__ __launch_bounds__(256, 1) void lstm_layer_kernel(
    const float* __restrict__ Whh,   // [4096][1024]
    const float* __restrict__ xp,    // [8192][4096] input proj + biases
    float* __restrict__ h_all,       // [8192][1024]
    float* hbuf,                     // [2*1024] ping-pong
    unsigned* ctr)                   // cumulative counter (one line)
{
    const int b   = blockIdx.x;
    const int tid = threadIdx.x;
    const int rg  = tid >> 6;        // gate 0..3 (i,f,g,o)
    const int cg  = tid & 63;        // 0..63
    const int lane = tid & 31;
    const int warp = tid >> 5;
    const int half = warp & 1;

    __shared__ float4 hs4[256];
    __shared__ float  red[4][2][8];
    __shared__ float  actbuf[32];

    // Weights into registers (R1 layout).
    float w[8][16];
#pragma unroll
    for (int i = 0; i < 8; i++) {
        const float* wr = Whh + (size_t)(rg * 1024 + b * 8 + i) * 1024 + cg * 4;
#pragma unroll
        for (int q = 0; q < 4; q++) {
            float4 t4 = *(const float4*)(wr + q * 256);
            w[i][q * 4 + 0] = t4.x; w[i][q * 4 + 1] = t4.y;
            w[i][q * 4 + 2] = t4.z; w[i][q * 4 + 3] = t4.w;
        }
    }

    float c_state = 0.0f;   // meaningful for tid < 8

    for (int t = 0; t < T_STEPS; ++t) {
        // x_proj prefetch: warp 0, lane (4*jj+g) -> gate g of element jj.
        float xv = 0.0f;
        if (tid < 32)
            xv = __ldcs(xp + (size_t)t * G_DIM + (tid & 3) * H_DIM + b * 8 + (tid >> 2));

        // Barrier: all blocks done step t-1  <=>  ctr >= 128*t.
        // Single poller per block; 128 spinners total on one L2 line.
        if (t > 0) {
            if (tid == 0) {
                const unsigned target = (unsigned)(NBLK) * (unsigned)t;
                while (ld_acq_u(ctr) < target) { }
            }
            __syncthreads();
        }

        // Stage h[t-1] (L1-bypassing; barrier above orders these reads).
        {
            const float4* hsrc = (const float4*)(hbuf + ((t + 1) & 1) * H_DIM);
            hs4[tid] = (t > 0) ? ld_cv4(hsrc + tid)
                               : make_float4(0.f, 0.f, 0.f, 0.f);
        }
        __syncthreads();

        // Mat-vec partials: 8 rows x 16 cols per thread (R1 order).
        float acc[8];
#pragma unroll
        for (int i = 0; i < 8; i++) acc[i] = 0.0f;
        float4 hq[4];
#pragma unroll
        for (int q = 0; q < 4; q++) hq[q] = hs4[cg + q * 64];
#pragma unroll
        for (int i = 0; i < 8; i++) {
#pragma unroll
            for (int q = 0; q < 4; q++) {
                acc[i] = fmaf(w[i][q * 4 + 0], hq[q].x, acc[i]);
                acc[i] = fmaf(w[i][q * 4 + 1], hq[q].y, acc[i]);
                acc[i] = fmaf(w[i][q * 4 + 2], hq[q].z, acc[i]);
                acc[i] = fmaf(w[i][q * 4 + 3], hq[q].w, acc[i]);
            }
        }
#pragma unroll
        for (int i = 0; i < 8; i++) {
#pragma unroll
            for (int off = 16; off > 0; off >>= 1)
                acc[i] += __shfl_xor_sync(0xFFFFFFFFu, acc[i], off);
        }
        if (lane == 0) {
#pragma unroll
            for (int i = 0; i < 8; i++) red[rg][half][i] = acc[i];
        }
        __syncthreads();

        // Tail (R7-proven, bit-exact): warp 0 computes 32 activations in
        // parallel; threads 0..7 combine with exact R1 expressions.
        if (tid < 32) {
            const int jj = tid >> 2;
            const int g  = tid & 3;
            float pre = red[g][0][jj] + red[g][1][jj] + xv;
            actbuf[tid] = (g == 2) ? tanhf(pre) : sigmoidf_(pre);
            __syncwarp(0xFFFFFFFFu);

            if (tid < 8) {
                float ig = actbuf[tid * 4 + 0];
                float fg = actbuf[tid * 4 + 1];
                float gg = actbuf[tid * 4 + 2];
                float og = actbuf[tid * 4 + 3];
                c_state = fg * c_state + ig * gg;
                float h  = og * tanhf(c_state);
                hbuf[(t & 1) * H_DIM + b * 8 + tid] = h;
                __syncwarp(0x000000FFu);
                if (tid == 0) {
                    fence_ar();                    // release: hbuf writes visible
                    red_add_relaxed(ctr, 1u);      // fire-and-forget arrive
                }
                __syncwarp(0x000000FFu);
                st_cg(h_all + (size_t)t * H_DIM + b * 8 + tid, h);
            }
        }
    }
}

// ---------------------------------------------------------------------------
// FC (109 outputs) + log_softmax. 8 timesteps per block, 256 threads.
// ---------------------------------------------------------------------------
__global__ __launch_bounds__(256) void fc_logsoftmax_kernel(
    const float* __restrict__ H,   // [8192][1024]
    const float* __restrict__ Wf,  // [109][1024]
    const float* __restrict__ bf,  // [109]
    float* __restrict__ out)       // [8192][109]
{
    __shared__ float ws[IN_DIM][68];
    __shared__ float hsm[8][68];
    __shared__ float lg[8][112];

    const int t0  = blockIdx.x * 8;
    const int tid = threadIdx.x;
    const int tt  = tid & 7;
    const int n4  = tid >> 3;

    float acc[4] = {0.f, 0.f, 0.f, 0.f};

    for (int kc = 0; kc < H_DIM; kc += 64) {
        for (int idx = tid; idx < IN_DIM * 16; idx += 256) {
            int n = idx >> 4, k4 = idx & 15;
            *(float4*)&ws[n][k4 * 4] = *(const float4*)&Wf[(size_t)n * H_DIM + kc + k4 * 4];
        }
        for (int idx = tid; idx < 8 * 16; idx += 256) {
            int r = idx >> 4, k4 = idx & 15;
            *(float4*)&hsm[r][k4 * 4] = *(const float4*)&H[(size_t)(t0 + r) * H_DIM + kc + k4 * 4];
        }
        __syncthreads();
#pragma unroll
        for (int k4 = 0; k4 < 16; k4++) {
            float4 hv = *(const float4*)&hsm[tt][k4 * 4];
#pragma unroll
            for (int i = 0; i < 4; i++) {
                int n = n4 + i * 32;
                if (n < IN_DIM) {
                    float4 wv = *(const float4*)&ws[n][k4 * 4];
                    acc[i] += hv.x * wv.x + hv.y * wv.y + hv.z * wv.z + hv.w * wv.w;
                }
            }
        }
        __syncthreads();
    }

#pragma unroll
    for (int i = 0; i < 4; i++) {
        int n = n4 + i * 32;
        if (n < IN_DIM) lg[tt][n] = acc[i] + bf[n];
    }
    __syncthreads();

    const int wp = tid >> 5, lane = tid & 31;
    {
        int t = wp;
        float v0 = (lane       < IN_DIM) ? lg[t][lane]       : -INFINITY;
        float v1 = (lane + 32  < IN_DIM) ? lg[t][lane + 32]  : -INFINITY;
        float v2 = (lane + 64  < IN_DIM) ? lg[t][lane + 64]  : -INFINITY;
        float v3 = (lane + 96  < IN_DIM) ? lg[t][lane + 96]  : -INFINITY;
        float mx = fmaxf(fmaxf(v0, v1), fmaxf(v2, v3));
#pragma unroll
        for (int o = 16; o > 0; o >>= 1) mx = fmaxf(mx, __shfl_xor_sync(0xFFFFFFFFu, mx, o));
        float se = expf(v0 - mx) + expf(v1 - mx) + expf(v2 - mx) + expf(v3 - mx);
#pragma unroll
        for (int o = 16; o > 0; o >>= 1) se += __shfl_xor_sync(0xFFFFFFFFu, se, o);
        float ls = mx + logf(se);
        size_t row = (size_t)(t0 + t) * IN_DIM;
        if (lane      < IN_DIM) out[row + lane]      = v0 - ls;
        if (lane + 32 < IN_DIM) out[row + lane + 32] = v1 - ls;
        if (lane + 64 < IN_DIM) out[row + lane + 64] = v2 - ls;
        if (lane + 96 < IN_DIM) out[row + lane + 96] = v3 - ls;
    }
}

// ---------------------------------------------------------------------------
// Launch
// ---------------------------------------------------------------------------
extern "C" void kernel_launch(void* const* d_in, const int* in_sizes, int n_in,
                              void* d_out, int out_size)
{
    const float* input  = (const float*)d_in[0];   // [8192,109]
    const float* W_ih0  = (const float*)d_in[1];   // [4096,109]
    const float* W_hh0  = (const float*)d_in[2];   // [4096,1024]
    const float* b_ih0  = (const float*)d_in[3];
    const float* b_hh0  = (const float*)d_in[4];
    const float* W_ih1  = (const float*)d_in[5];   // [4096,1024]
    const float* W_hh1  = (const float*)d_in[6];   // [4096,1024]
    const float* b_ih1  = (const float*)d_in[7];
    const float* b_hh1  = (const float*)d_in[8];
    const float* fc_w   = (const float*)d_in[9];   // [109,1024]
    const float* fc_b   = (const float*)d_in[10];
    float* out = (float*)d_out;

    static float* p_xproj = nullptr;
    static float* p_h0 = nullptr;
    static float* p_h1 = nullptr;
    static float* p_hbuf = nullptr;
    static unsigned* p_ctr = nullptr;
    if (!p_xproj) {
        cudaGetSymbolAddress((void**)&p_xproj, g_xproj);
        cudaGetSymbolAddress((void**)&p_h0,    g_h0);
        cudaGetSymbolAddress((void**)&p_h1,    g_h1);
        cudaGetSymbolAddress((void**)&p_hbuf,  g_hbuf);
        cudaGetSymbolAddress((void**)&p_ctr,   g_ctr);
    }

    // 1) reset counters + h ping-pong buffers
    init_kernel<<<17, 256>>>();

    // 2) x_proj0 = input @ W_ih0^T + b_ih0 + b_hh0  (K=109)
    {
        dim3 grid(G_DIM / 128, T_STEPS / 128);
        gemm_nt_bias<<<grid, 256>>>(input, W_ih0, b_ih0, b_hh0,
                                    p_xproj, G_DIM, IN_DIM);
    }

    // 3) layer-0 recurrence
    lstm_layer_kernel<<<NBLK, 256>>>(W_hh0, p_xproj, p_h0,
                                     p_hbuf + 0, p_ctr + 0);

    // 4) x_proj1 = h0 @ W_ih1^T + b_ih1 + b_hh1
    {
        dim3 grid(G_DIM / 128, T_STEPS / 128);
        gemm_nt_bias<<<grid, 256>>>(p_h0, W_ih1, b_ih1, b_hh1,
                                    p_xproj, G_DIM, H_DIM);
    }

    // 5) layer-1 recurrence
    lstm_layer_kernel<<<NBLK, 256>>>(W_hh1, p_xproj, p_h1,
                                     p_hbuf + 2 * H_DIM, p_ctr + 32);

    // 6) FC + log_softmax
    fc_logsoftmax_kernel<<<T_STEPS / 8, 256>>>(p_h1, fc_w, fc_b, out);
}

// round 10
// speedup vs baseline: 1.8445x; 1.0555x over previous
#include <cuda_runtime.h>
#include <cstdint>
#include <math.h>

// ---------------------------------------------------------------------------
// Problem dims
// ---------------------------------------------------------------------------
#define T_STEPS 8192
#define IN_DIM  109
#define H_DIM   1024
#define G_DIM   4096   // 4*H
#define NBLK    128    // persistent blocks (<=148 SMs, 1 CTA/SM -> co-resident)

// ---------------------------------------------------------------------------
// Scratch (static device allocations; no cudaMalloc allowed)
// ---------------------------------------------------------------------------
__device__ float g_xproj[(size_t)T_STEPS * G_DIM];   // reused for both layers
__device__ float g_h0[(size_t)T_STEPS * H_DIM];
__device__ float g_h1[(size_t)T_STEPS * H_DIM];
__device__ float g_hbuf[2][2 * H_DIM];               // [layer][parity*1024 + j]
// Cumulative step counters, one per layer, on separate 128B lines.
// Block adds 1 after each step (and one final bump): ctr == 128*t  <=>  all
// blocks completed step t-1. Max value 128*(T_STEPS+1).
__device__ unsigned g_ctr[64];                       // [0] layer0, [32] layer1

// ---------------------------------------------------------------------------
// Memory-order helpers
// ---------------------------------------------------------------------------
__device__ __forceinline__ unsigned ld_acq_u(const unsigned* p) {
    unsigned v;
    asm volatile("ld.acquire.gpu.b32 %0, [%1];" : "=r"(v) : "l"(p) : "memory");
    return v;
}
__device__ __forceinline__ void red_add_release(unsigned* p, unsigned v) {
    asm volatile("red.release.gpu.global.add.u32 [%0], %1;" :: "l"(p), "r"(v) : "memory");
}
__device__ __forceinline__ float4 ld_cv4(const float4* p) {
    float4 v;
    asm volatile("ld.global.cv.v4.f32 {%0,%1,%2,%3}, [%4];"
                 : "=f"(v.x), "=f"(v.y), "=f"(v.z), "=f"(v.w) : "l"(p) : "memory");
    return v;
}
__device__ __forceinline__ void st_cg(float* p, float v) {
    asm volatile("st.global.cg.f32 [%0], %1;" :: "l"(p), "f"(v) : "memory");
}
__device__ __forceinline__ float sigmoidf_(float x) {
    return 1.0f / (1.0f + expf(-x));   // PRECISE (R1-proven)
}

// ---------------------------------------------------------------------------
// Init: zero counters + hbuf (every launch; graph replays reuse statics)
// ---------------------------------------------------------------------------
__global__ void init_kernel() {
    int i = blockIdx.x * blockDim.x + threadIdx.x;
    if (i < 64) g_ctr[i] = 0u;
    if (i < 2 * 2 * H_DIM) ((float*)g_hbuf)[i] = 0.0f;
}

// ---------------------------------------------------------------------------
// GEMM tile body: C[m0..+128][n0..+128] = A@B^T + bias1 + bias2 (R1-proven)
// ---------------------------------------------------------------------------
__device__ void gemm_tile_body(
    const float* A, const float* B,
    const float* bias1, const float* bias2,
    float* C, int N, int K, int m0, int n0)
{
    __shared__ float As[8][132];
    __shared__ float Bs[8][132];

    const int tid = threadIdx.x;
    const int lr  = tid >> 1;
    const int lk4 = (tid & 1) * 4;
    const int ty  = tid >> 4;
    const int tx  = tid & 15;

    float acc[8][8];
#pragma unroll
    for (int i = 0; i < 8; i++)
#pragma unroll
        for (int j = 0; j < 8; j++) acc[i][j] = 0.0f;

    for (int k0 = 0; k0 < K; k0 += 8) {
#pragma unroll
        for (int e = 0; e < 4; e++) {
            int k = k0 + lk4 + e;
            float av = 0.0f, bv = 0.0f;
            if (k < K) {
                av = A[(size_t)(m0 + lr) * K + k];
                bv = B[(size_t)(n0 + lr) * K + k];
            }
            As[lk4 + e][lr] = av;
            Bs[lk4 + e][lr] = bv;
        }
        __syncthreads();
#pragma unroll
        for (int kk = 0; kk < 8; kk++) {
            float a[8], b[8];
            float4 a0 = *(const float4*)&As[kk][ty * 8];
            float4 a1 = *(const float4*)&As[kk][ty * 8 + 4];
            float4 b0 = *(const float4*)&Bs[kk][tx * 8];
            float4 b1 = *(const float4*)&Bs[kk][tx * 8 + 4];
            a[0]=a0.x; a[1]=a0.y; a[2]=a0.z; a[3]=a0.w;
            a[4]=a1.x; a[5]=a1.y; a[6]=a1.z; a[7]=a1.w;
            b[0]=b0.x; b[1]=b0.y; b[2]=b0.z; b[3]=b0.w;
            b[4]=b1.x; b[5]=b1.y; b[6]=b1.z; b[7]=b1.w;
#pragma unroll
            for (int i = 0; i < 8; i++)
#pragma unroll
                for (int j = 0; j < 8; j++)
                    acc[i][j] = fmaf(a[i], b[j], acc[i][j]);
        }
        __syncthreads();
    }

#pragma unroll
    for (int i = 0; i < 8; i++) {
        size_t row = (size_t)(m0 + ty * 8 + i) * N;
#pragma unroll
        for (int j = 0; j < 8; j++) {
            int n = n0 + tx * 8 + j;
            C[row + n] = acc[i][j] + bias1[n] + bias2[n];
        }
    }
}

// Standalone GEMM (x_proj0, K=109)
__global__ __launch_bounds__(256) void gemm_nt_bias(
    const float* __restrict__ A, const float* __restrict__ B,
    const float* __restrict__ bias1, const float* __restrict__ bias2,
    float* __restrict__ C, int N, int K)
{
    gemm_tile_body(A, B, bias1, bias2, C, N, K, blockIdx.y * 128, blockIdx.x * 128);
}

// ---------------------------------------------------------------------------
// LSTM recurrence body — R9-proven: R1-exact numerics, single-counter barrier,
// 1 poller/block; release-RED arrive; final bump publishes tail h rows.
// ---------------------------------------------------------------------------
__device__ void lstm_body(
    const float* __restrict__ Whh,   // [4096][1024]
    const float* xp,                 // [8192][4096] (may alias GEMM output)
    float* h_all,                    // [8192][1024]
    float* hbuf,                     // [2*1024]
    unsigned* ctr)
{
    const int b   = blockIdx.x;
    const int tid = threadIdx.x;
    const int rg  = tid >> 6;        // gate 0..3 (i,f,g,o)
    const int cg  = tid & 63;        // 0..63
    const int lane = tid & 31;
    const int warp = tid >> 5;
    const int half = warp & 1;

    __shared__ float4 hs4[256];
    __shared__ float  red[4][2][8];
    __shared__ float  actbuf[32];

    // Weights into registers (R1 layout).
    float w[8][16];
#pragma unroll
    for (int i = 0; i < 8; i++) {
        const float* wr = Whh + (size_t)(rg * 1024 + b * 8 + i) * 1024 + cg * 4;
#pragma unroll
        for (int q = 0; q < 4; q++) {
            float4 t4 = *(const float4*)(wr + q * 256);
            w[i][q * 4 + 0] = t4.x; w[i][q * 4 + 1] = t4.y;
            w[i][q * 4 + 2] = t4.z; w[i][q * 4 + 3] = t4.w;
        }
    }

    float c_state = 0.0f;   // meaningful for tid < 8

    for (int t = 0; t < T_STEPS; ++t) {
        // x_proj prefetch: warp 0, lane (4*jj+g) -> gate g of element jj.
        float xv = 0.0f;
        if (tid < 32)
            xv = __ldcs(xp + (size_t)t * G_DIM + (tid & 3) * H_DIM + b * 8 + (tid >> 2));

        // Barrier: ctr >= 128*t  <=>  all blocks completed step t-1.
        if (t > 0) {
            if (tid == 0) {
                const unsigned target = (unsigned)NBLK * (unsigned)t;
                while (ld_acq_u(ctr) < target) { }
            }
            __syncthreads();
        }

        // Stage h[t-1] (L1-bypassing; the acquire above orders these reads).
        {
            const float4* hsrc = (const float4*)(hbuf + ((t + 1) & 1) * H_DIM);
            hs4[tid] = (t > 0) ? ld_cv4(hsrc + tid)
                               : make_float4(0.f, 0.f, 0.f, 0.f);
        }
        __syncthreads();

        // Mat-vec partials: 8 rows x 16 cols per thread (R1 order).
        float acc[8];
#pragma unroll
        for (int i = 0; i < 8; i++) acc[i] = 0.0f;
        float4 hq[4];
#pragma unroll
        for (int q = 0; q < 4; q++) hq[q] = hs4[cg + q * 64];
#pragma unroll
        for (int i = 0; i < 8; i++) {
#pragma unroll
            for (int q = 0; q < 4; q++) {
                acc[i] = fmaf(w[i][q * 4 + 0], hq[q].x, acc[i]);
                acc[i] = fmaf(w[i][q * 4 + 1], hq[q].y, acc[i]);
                acc[i] = fmaf(w[i][q * 4 + 2], hq[q].z, acc[i]);
                acc[i] = fmaf(w[i][q * 4 + 3], hq[q].w, acc[i]);
            }
        }
#pragma unroll
        for (int i = 0; i < 8; i++) {
#pragma unroll
            for (int off = 16; off > 0; off >>= 1)
                acc[i] += __shfl_xor_sync(0xFFFFFFFFu, acc[i], off);
        }
        if (lane == 0) {
#pragma unroll
            for (int i = 0; i < 8; i++) red[rg][half][i] = acc[i];
        }
        __syncthreads();

        // Tail (bit-exact R1 math, parallel activations).
        if (tid < 32) {
            const int jj = tid >> 2;
            const int g  = tid & 3;
            float pre = red[g][0][jj] + red[g][1][jj] + xv;
            actbuf[tid] = (g == 2) ? tanhf(pre) : sigmoidf_(pre);
            __syncwarp(0xFFFFFFFFu);

            if (tid < 8) {
                float ig = actbuf[tid * 4 + 0];
                float fg = actbuf[tid * 4 + 1];
                float gg = actbuf[tid * 4 + 2];
                float og = actbuf[tid * 4 + 3];
                c_state = fg * c_state + ig * gg;
                float h  = og * tanhf(c_state);
                hbuf[(t & 1) * H_DIM + b * 8 + tid] = h;
                __syncwarp(0x000000FFu);
                if (tid == 0) {
                    red_add_release(ctr, 1u);      // release-arrive (hbuf visible)
                }
                __syncwarp(0x000000FFu);
                st_cg(h_all + (size_t)t * H_DIM + b * 8 + tid, h);
            }
        }
    }

    // Final bump: arrival T+1 publishes the last h_all rows (stored after the
    // last in-loop RED) to gated consumer CTAs. ctr max -> 128*(T_STEPS+1).
    __syncthreads();
    if (tid == 0) {
        red_add_release(ctr, 1u);
    }
}

// ---------------------------------------------------------------------------
// Fused kernel A: blocks 0..127 = layer-0 recurrence. Blocks 128.. = gated
// GEMM1 tiles (xproj1 = h0 @ W_ih1^T + biases) into g_xproj.
// Gate ctr0 >= 128*(m0+129): (a) h0 rows <= m0+127 visible (covered by the
// release of arrival m0+129); (b) xproj0 rows <= m0+128 consumed -> WAR-safe.
// One poller per tile CTA with ~1us backoff -> no counter-line storm.
// ---------------------------------------------------------------------------
__global__ __launch_bounds__(256, 1) void fused_l0_gemm1(
    const float* __restrict__ Whh0,
    float* xproj,
    float* __restrict__ h0,
    float* hbuf, unsigned* ctr,
    const float* __restrict__ Wih1,
    const float* __restrict__ b_ih1, const float* __restrict__ b_hh1)
{
    if (blockIdx.x < NBLK) {
        lstm_body(Whh0, xproj, h0, hbuf, ctr);
    } else {
        const int tile = blockIdx.x - NBLK;       // 0..2047
        const int n0 = (tile & 31) * 128;         // G_DIM/128 = 32
        const int m0 = (tile >> 5) * 128;         // T_STEPS/128 = 64
        const unsigned target = (unsigned)NBLK * (unsigned)(m0 + 129);
        if (threadIdx.x == 0) {
            while (ld_acq_u(ctr) < target) { __nanosleep(1024); }
        }
        __syncthreads();
        gemm_tile_body(h0, Wih1, b_ih1, b_hh1, xproj, G_DIM, H_DIM, m0, n0);
    }
}

// ---------------------------------------------------------------------------
// FC (109 outputs) + log_softmax body. 8 timesteps per block.
// ---------------------------------------------------------------------------
__device__ void fc_body(
    const float* __restrict__ H, const float* __restrict__ Wf,
    const float* __restrict__ bf, float* __restrict__ out, int t0)
{
    __shared__ float ws[IN_DIM][68];
    __shared__ float hsm[8][68];
    __shared__ float lg[8][112];

    const int tid = threadIdx.x;
    const int tt  = tid & 7;
    const int n4  = tid >> 3;

    float acc[4] = {0.f, 0.f, 0.f, 0.f};

    for (int kc = 0; kc < H_DIM; kc += 64) {
        for (int idx = tid; idx < IN_DIM * 16; idx += 256) {
            int n = idx >> 4, k4 = idx & 15;
            *(float4*)&ws[n][k4 * 4] = *(const float4*)&Wf[(size_t)n * H_DIM + kc + k4 * 4];
        }
        for (int idx = tid; idx < 8 * 16; idx += 256) {
            int r = idx >> 4, k4 = idx & 15;
            *(float4*)&hsm[r][k4 * 4] = *(const float4*)&H[(size_t)(t0 + r) * H_DIM + kc + k4 * 4];
        }
        __syncthreads();
#pragma unroll
        for (int k4 = 0; k4 < 16; k4++) {
            float4 hv = *(const float4*)&hsm[tt][k4 * 4];
#pragma unroll
            for (int i = 0; i < 4; i++) {
                int n = n4 + i * 32;
                if (n < IN_DIM) {
                    float4 wv = *(const float4*)&ws[n][k4 * 4];
                    acc[i] += hv.x * wv.x + hv.y * wv.y + hv.z * wv.z + hv.w * wv.w;
                }
            }
        }
        __syncthreads();
    }

#pragma unroll
    for (int i = 0; i < 4; i++) {
        int n = n4 + i * 32;
        if (n < IN_DIM) lg[tt][n] = acc[i] + bf[n];
    }
    __syncthreads();

    const int wp = tid >> 5, lane = tid & 31;
    {
        int t = wp;
        float v0 = (lane       < IN_DIM) ? lg[t][lane]       : -INFINITY;
        float v1 = (lane + 32  < IN_DIM) ? lg[t][lane + 32]  : -INFINITY;
        float v2 = (lane + 64  < IN_DIM) ? lg[t][lane + 64]  : -INFINITY;
        float v3 = (lane + 96  < IN_DIM) ? lg[t][lane + 96]  : -INFINITY;
        float mx = fmaxf(fmaxf(v0, v1), fmaxf(v2, v3));
#pragma unroll
        for (int o = 16; o > 0; o >>= 1) mx = fmaxf(mx, __shfl_xor_sync(0xFFFFFFFFu, mx, o));
        float se = expf(v0 - mx) + expf(v1 - mx) + expf(v2 - mx) + expf(v3 - mx);
#pragma unroll
        for (int o = 16; o > 0; o >>= 1) se += __shfl_xor_sync(0xFFFFFFFFu, se, o);
        float ls = mx + logf(se);
        size_t row = (size_t)(t0 + t) * IN_DIM;
        if (lane      < IN_DIM) out[row + lane]      = v0 - ls;
        if (lane + 32 < IN_DIM) out[row + lane + 32] = v1 - ls;
        if (lane + 64 < IN_DIM) out[row + lane + 64] = v2 - ls;
        if (lane + 96 < IN_DIM) out[row + lane + 96] = v3 - ls;
    }
}

// ---------------------------------------------------------------------------
// Fused kernel B: blocks 0..127 = layer-1 recurrence. Blocks 128..1151 = gated
// FC+log_softmax tiles (h1 rows t0..t0+7 visible once ctr1 >= 128*(t0+9)).
// ---------------------------------------------------------------------------
__global__ __launch_bounds__(256, 1) void fused_l1_fc(
    const float* __restrict__ Whh1,
    const float* __restrict__ xproj,
    float* __restrict__ h1,
    float* hbuf, unsigned* ctr,
    const float* __restrict__ fc_w, const float* __restrict__ fc_b,
    float* __restrict__ out)
{
    if (blockIdx.x < NBLK) {
        lstm_body(Whh1, xproj, h1, hbuf, ctr);
    } else {
        const int t0 = (blockIdx.x - NBLK) * 8;
        const unsigned target = (unsigned)NBLK * (unsigned)(t0 + 9);
        if (threadIdx.x == 0) {
            while (ld_acq_u(ctr) < target) { __nanosleep(1024); }
        }
        __syncthreads();
        fc_body(h1, fc_w, fc_b, out, t0);
    }
}

// ---------------------------------------------------------------------------
// Launch
// ---------------------------------------------------------------------------
extern "C" void kernel_launch(void* const* d_in, const int* in_sizes, int n_in,
                              void* d_out, int out_size)
{
    const float* input  = (const float*)d_in[0];   // [8192,109]
    const float* W_ih0  = (const float*)d_in[1];   // [4096,109]
    const float* W_hh0  = (const float*)d_in[2];   // [4096,1024]
    const float* b_ih0  = (const float*)d_in[3];
    const float* b_hh0  = (const float*)d_in[4];
    const float* W_ih1  = (const float*)d_in[5];   // [4096,1024]
    const float* W_hh1  = (const float*)d_in[6];   // [4096,1024]
    const float* b_ih1  = (const float*)d_in[7];
    const float* b_hh1  = (const float*)d_in[8];
    const float* fc_w   = (const float*)d_in[9];   // [109,1024]
    const float* fc_b   = (const float*)d_in[10];
    float* out = (float*)d_out;

    static float* p_xproj = nullptr;
    static float* p_h0 = nullptr;
    static float* p_h1 = nullptr;
    static float* p_hbuf = nullptr;
    static unsigned* p_ctr = nullptr;
    if (!p_xproj) {
        cudaGetSymbolAddress((void**)&p_xproj, g_xproj);
        cudaGetSymbolAddress((void**)&p_h0,    g_h0);
        cudaGetSymbolAddress((void**)&p_h1,    g_h1);
        cudaGetSymbolAddress((void**)&p_hbuf,  g_hbuf);
        cudaGetSymbolAddress((void**)&p_ctr,   g_ctr);
    }

    // 1) reset counters + h ping-pong buffers
    init_kernel<<<17, 256>>>();

    // 2) x_proj0 = input @ W_ih0^T + b_ih0 + b_hh0  (K=109)
    {
        dim3 grid(G_DIM / 128, T_STEPS / 128);
        gemm_nt_bias<<<grid, 256>>>(input, W_ih0, b_ih0, b_hh0,
                                    p_xproj, G_DIM, IN_DIM);
    }

    // 3) layer-0 recurrence + gated GEMM1 (xproj1) overlapped
    fused_l0_gemm1<<<NBLK + 2048, 256>>>(W_hh0, p_xproj, p_h0,
                                         p_hbuf + 0, p_ctr + 0,
                                         W_ih1, b_ih1, b_hh1);

    // 4) layer-1 recurrence + gated FC/log_softmax overlapped
    fused_l1_fc<<<NBLK + T_STEPS / 8, 256>>>(W_hh1, p_xproj, p_h1,
                                             p_hbuf + 2 * H_DIM, p_ctr + 32,
                                             fc_w, fc_b, out);
}

// round 11
// speedup vs baseline: 1.8449x; 1.0003x over previous
#include <cuda_runtime.h>
#include <cstdint>
#include <math.h>

// ---------------------------------------------------------------------------
// Problem dims
// ---------------------------------------------------------------------------
#define T_STEPS 8192
#define IN_DIM  109
#define H_DIM   1024
#define G_DIM   4096   // 4*H
#define NBLK    128    // persistent blocks (<=148 SMs, 1 CTA/SM -> co-resident)

// ---------------------------------------------------------------------------
// Scratch (static device allocations; no cudaMalloc allowed)
// ---------------------------------------------------------------------------
__device__ float g_xproj[(size_t)T_STEPS * G_DIM];   // reused for both layers
__device__ float g_h0[(size_t)T_STEPS * H_DIM];
__device__ float g_h1[(size_t)T_STEPS * H_DIM];
__device__ float g_hbuf[2][2 * H_DIM];               // [layer][parity*1024 + j]
// Cumulative step counters, one per layer, on separate 128B lines.
// Block adds 1 after each step (and one final bump): ctr == 128*t  <=>  all
// blocks completed step t-1. Max value 128*(T_STEPS+1).
__device__ unsigned g_ctr[64];                       // [0] layer0, [32] layer1

// ---------------------------------------------------------------------------
// Memory-order helpers
// ---------------------------------------------------------------------------
__device__ __forceinline__ unsigned ld_acq_u(const unsigned* p) {
    unsigned v;
    asm volatile("ld.acquire.gpu.b32 %0, [%1];" : "=r"(v) : "l"(p) : "memory");
    return v;
}
__device__ __forceinline__ void red_add_release(unsigned* p, unsigned v) {
    asm volatile("red.release.gpu.global.add.u32 [%0], %1;" :: "l"(p), "r"(v) : "memory");
}
__device__ __forceinline__ float4 ld_cv4(const float4* p) {
    float4 v;
    asm volatile("ld.global.cv.v4.f32 {%0,%1,%2,%3}, [%4];"
                 : "=f"(v.x), "=f"(v.y), "=f"(v.z), "=f"(v.w) : "l"(p) : "memory");
    return v;
}
__device__ __forceinline__ void st_cg(float* p, float v) {
    asm volatile("st.global.cg.f32 [%0], %1;" :: "l"(p), "f"(v) : "memory");
}
__device__ __forceinline__ float sigmoidf_(float x) {
    return 1.0f / (1.0f + expf(-x));   // PRECISE (R1-proven)
}

// ---------------------------------------------------------------------------
// Init: zero counters + hbuf (every launch; graph replays reuse statics)
// ---------------------------------------------------------------------------
__global__ void init_kernel() {
    int i = blockIdx.x * blockDim.x + threadIdx.x;
    if (i < 64) g_ctr[i] = 0u;
    if (i < 2 * 2 * H_DIM) ((float*)g_hbuf)[i] = 0.0f;
}

// ---------------------------------------------------------------------------
// GEMM tile body: C[m0..+128][n0..+128] = A@B^T + bias1 + bias2 (R1-proven)
// ---------------------------------------------------------------------------
__device__ void gemm_tile_body(
    const float* A, const float* B,
    const float* bias1, const float* bias2,
    float* C, int N, int K, int m0, int n0)
{
    __shared__ float As[8][132];
    __shared__ float Bs[8][132];

    const int tid = threadIdx.x;
    const int lr  = tid >> 1;
    const int lk4 = (tid & 1) * 4;
    const int ty  = tid >> 4;
    const int tx  = tid & 15;

    float acc[8][8];
#pragma unroll
    for (int i = 0; i < 8; i++)
#pragma unroll
        for (int j = 0; j < 8; j++) acc[i][j] = 0.0f;

    for (int k0 = 0; k0 < K; k0 += 8) {
#pragma unroll
        for (int e = 0; e < 4; e++) {
            int k = k0 + lk4 + e;
            float av = 0.0f, bv = 0.0f;
            if (k < K) {
                av = A[(size_t)(m0 + lr) * K + k];
                bv = B[(size_t)(n0 + lr) * K + k];
            }
            As[lk4 + e][lr] = av;
            Bs[lk4 + e][lr] = bv;
        }
        __syncthreads();
#pragma unroll
        for (int kk = 0; kk < 8; kk++) {
            float a[8], b[8];
            float4 a0 = *(const float4*)&As[kk][ty * 8];
            float4 a1 = *(const float4*)&As[kk][ty * 8 + 4];
            float4 b0 = *(const float4*)&Bs[kk][tx * 8];
            float4 b1 = *(const float4*)&Bs[kk][tx * 8 + 4];
            a[0]=a0.x; a[1]=a0.y; a[2]=a0.z; a[3]=a0.w;
            a[4]=a1.x; a[5]=a1.y; a[6]=a1.z; a[7]=a1.w;
            b[0]=b0.x; b[1]=b0.y; b[2]=b0.z; b[3]=b0.w;
            b[4]=b1.x; b[5]=b1.y; b[6]=b1.z; b[7]=b1.w;
#pragma unroll
            for (int i = 0; i < 8; i++)
#pragma unroll
                for (int j = 0; j < 8; j++)
                    acc[i][j] = fmaf(a[i], b[j], acc[i][j]);
        }
        __syncthreads();
    }

#pragma unroll
    for (int i = 0; i < 8; i++) {
        size_t row = (size_t)(m0 + ty * 8 + i) * N;
#pragma unroll
        for (int j = 0; j < 8; j++) {
            int n = n0 + tx * 8 + j;
            C[row + n] = acc[i][j] + bias1[n] + bias2[n];
        }
    }
}

// Standalone GEMM (x_proj0, K=109)
__global__ __launch_bounds__(256) void gemm_nt_bias(
    const float* __restrict__ A, const float* __restrict__ B,
    const float* __restrict__ bias1, const float* __restrict__ bias2,
    float* __restrict__ C, int N, int K)
{
    gemm_tile_body(A, B, bias1, bias2, C, N, K, blockIdx.y * 128, blockIdx.x * 128);
}

// ---------------------------------------------------------------------------
// LSTM recurrence body — R9-proven: R1-exact numerics, single-counter barrier,
// 1 poller/block; release-RED arrive; final bump publishes tail h rows.
// ---------------------------------------------------------------------------
__device__ void lstm_body(
    const float* __restrict__ Whh,   // [4096][1024]
    const float* xp,                 // [8192][4096] (may alias GEMM output)
    float* h_all,                    // [8192][1024]
    float* hbuf,                     // [2*1024]
    unsigned* ctr)
{
    const int b   = blockIdx.x;
    const int tid = threadIdx.x;
    const int rg  = tid >> 6;        // gate 0..3 (i,f,g,o)
    const int cg  = tid & 63;        // 0..63
    const int lane = tid & 31;
    const int warp = tid >> 5;
    const int half = warp & 1;

    __shared__ float4 hs4[256];
    __shared__ float  red[4][2][8];
    __shared__ float  actbuf[32];

    // Weights into registers (R1 layout).
    float w[8][16];
#pragma unroll
    for (int i = 0; i < 8; i++) {
        const float* wr = Whh + (size_t)(rg * 1024 + b * 8 + i) * 1024 + cg * 4;
#pragma unroll
        for (int q = 0; q < 4; q++) {
            float4 t4 = *(const float4*)(wr + q * 256);
            w[i][q * 4 + 0] = t4.x; w[i][q * 4 + 1] = t4.y;
            w[i][q * 4 + 2] = t4.z; w[i][q * 4 + 3] = t4.w;
        }
    }

    float c_state = 0.0f;   // meaningful for tid < 8

    for (int t = 0; t < T_STEPS; ++t) {
        // x_proj prefetch: warp 0, lane (4*jj+g) -> gate g of element jj.
        float xv = 0.0f;
        if (tid < 32)
            xv = __ldcs(xp + (size_t)t * G_DIM + (tid & 3) * H_DIM + b * 8 + (tid >> 2));

        // Barrier: ctr >= 128*t  <=>  all blocks completed step t-1.
        if (t > 0) {
            if (tid == 0) {
                const unsigned target = (unsigned)NBLK * (unsigned)t;
                while (ld_acq_u(ctr) < target) { }
            }
            __syncthreads();
        }

        // Stage h[t-1] (L1-bypassing; the acquire above orders these reads).
        {
            const float4* hsrc = (const float4*)(hbuf + ((t + 1) & 1) * H_DIM);
            hs4[tid] = (t > 0) ? ld_cv4(hsrc + tid)
                               : make_float4(0.f, 0.f, 0.f, 0.f);
        }
        __syncthreads();

        // Mat-vec partials: 8 rows x 16 cols per thread (R1 order).
        float acc[8];
#pragma unroll
        for (int i = 0; i < 8; i++) acc[i] = 0.0f;
        float4 hq[4];
#pragma unroll
        for (int q = 0; q < 4; q++) hq[q] = hs4[cg + q * 64];
#pragma unroll
        for (int i = 0; i < 8; i++) {
#pragma unroll
            for (int q = 0; q < 4; q++) {
                acc[i] = fmaf(w[i][q * 4 + 0], hq[q].x, acc[i]);
                acc[i] = fmaf(w[i][q * 4 + 1], hq[q].y, acc[i]);
                acc[i] = fmaf(w[i][q * 4 + 2], hq[q].z, acc[i]);
                acc[i] = fmaf(w[i][q * 4 + 3], hq[q].w, acc[i]);
            }
        }
#pragma unroll
        for (int i = 0; i < 8; i++) {
#pragma unroll
            for (int off = 16; off > 0; off >>= 1)
                acc[i] += __shfl_xor_sync(0xFFFFFFFFu, acc[i], off);
        }
        if (lane == 0) {
#pragma unroll
            for (int i = 0; i < 8; i++) red[rg][half][i] = acc[i];
        }
        __syncthreads();

        // Tail (bit-exact R1 math, parallel activations).
        if (tid < 32) {
            const int jj = tid >> 2;
            const int g  = tid & 3;
            float pre = red[g][0][jj] + red[g][1][jj] + xv;
            actbuf[tid] = (g == 2) ? tanhf(pre) : sigmoidf_(pre);
            __syncwarp(0xFFFFFFFFu);

            if (tid < 8) {
                float ig = actbuf[tid * 4 + 0];
                float fg = actbuf[tid * 4 + 1];
                float gg = actbuf[tid * 4 + 2];
                float og = actbuf[tid * 4 + 3];
                c_state = fg * c_state + ig * gg;
                float h  = og * tanhf(c_state);
                hbuf[(t & 1) * H_DIM + b * 8 + tid] = h;
                __syncwarp(0x000000FFu);
                if (tid == 0) {
                    red_add_release(ctr, 1u);      // release-arrive (hbuf visible)
                }
                __syncwarp(0x000000FFu);
                st_cg(h_all + (size_t)t * H_DIM + b * 8 + tid, h);
            }
        }
    }

    // Final bump: arrival T+1 publishes the last h_all rows (stored after the
    // last in-loop RED) to gated consumer CTAs. ctr max -> 128*(T_STEPS+1).
    __syncthreads();
    if (tid == 0) {
        red_add_release(ctr, 1u);
    }
}

// ---------------------------------------------------------------------------
// Fused kernel A: blocks 0..127 = layer-0 recurrence. Blocks 128.. = gated
// GEMM1 tiles (xproj1 = h0 @ W_ih1^T + biases) into g_xproj.
// Gate ctr0 >= 128*(m0+129): (a) h0 rows <= m0+127 visible (covered by the
// release of arrival m0+129); (b) xproj0 rows <= m0+128 consumed -> WAR-safe.
// One poller per tile CTA with ~1us backoff -> no counter-line storm.
// ---------------------------------------------------------------------------
__global__ __launch_bounds__(256, 1) void fused_l0_gemm1(
    const float* __restrict__ Whh0,
    float* xproj,
    float* __restrict__ h0,
    float* hbuf, unsigned* ctr,
    const float* __restrict__ Wih1,
    const float* __restrict__ b_ih1, const float* __restrict__ b_hh1)
{
    if (blockIdx.x < NBLK) {
        lstm_body(Whh0, xproj, h0, hbuf, ctr);
    } else {
        const int tile = blockIdx.x - NBLK;       // 0..2047
        const int n0 = (tile & 31) * 128;         // G_DIM/128 = 32
        const int m0 = (tile >> 5) * 128;         // T_STEPS/128 = 64
        const unsigned target = (unsigned)NBLK * (unsigned)(m0 + 129);
        if (threadIdx.x == 0) {
            while (ld_acq_u(ctr) < target) { __nanosleep(1024); }
        }
        __syncthreads();
        gemm_tile_body(h0, Wih1, b_ih1, b_hh1, xproj, G_DIM, H_DIM, m0, n0);
    }
}

// ---------------------------------------------------------------------------
// FC (109 outputs) + log_softmax body. 8 timesteps per block.
// ---------------------------------------------------------------------------
__device__ void fc_body(
    const float* __restrict__ H, const float* __restrict__ Wf,
    const float* __restrict__ bf, float* __restrict__ out, int t0)
{
    __shared__ float ws[IN_DIM][68];
    __shared__ float hsm[8][68];
    __shared__ float lg[8][112];

    const int tid = threadIdx.x;
    const int tt  = tid & 7;
    const int n4  = tid >> 3;

    float acc[4] = {0.f, 0.f, 0.f, 0.f};

    for (int kc = 0; kc < H_DIM; kc += 64) {
        for (int idx = tid; idx < IN_DIM * 16; idx += 256) {
            int n = idx >> 4, k4 = idx & 15;
            *(float4*)&ws[n][k4 * 4] = *(const float4*)&Wf[(size_t)n * H_DIM + kc + k4 * 4];
        }
        for (int idx = tid; idx < 8 * 16; idx += 256) {
            int r = idx >> 4, k4 = idx & 15;
            *(float4*)&hsm[r][k4 * 4] = *(const float4*)&H[(size_t)(t0 + r) * H_DIM + kc + k4 * 4];
        }
        __syncthreads();
#pragma unroll
        for (int k4 = 0; k4 < 16; k4++) {
            float4 hv = *(const float4*)&hsm[tt][k4 * 4];
#pragma unroll
            for (int i = 0; i < 4; i++) {
                int n = n4 + i * 32;
                if (n < IN_DIM) {
                    float4 wv = *(const float4*)&ws[n][k4 * 4];
                    acc[i] += hv.x * wv.x + hv.y * wv.y + hv.z * wv.z + hv.w * wv.w;
                }
            }
        }
        __syncthreads();
    }

#pragma unroll
    for (int i = 0; i < 4; i++) {
        int n = n4 + i * 32;
        if (n < IN_DIM) lg[tt][n] = acc[i] + bf[n];
    }
    __syncthreads();

    const int wp = tid >> 5, lane = tid & 31;
    {
        int t = wp;
        float v0 = (lane       < IN_DIM) ? lg[t][lane]       : -INFINITY;
        float v1 = (lane + 32  < IN_DIM) ? lg[t][lane + 32]  : -INFINITY;
        float v2 = (lane + 64  < IN_DIM) ? lg[t][lane + 64]  : -INFINITY;
        float v3 = (lane + 96  < IN_DIM) ? lg[t][lane + 96]  : -INFINITY;
        float mx = fmaxf(fmaxf(v0, v1), fmaxf(v2, v3));
#pragma unroll
        for (int o = 16; o > 0; o >>= 1) mx = fmaxf(mx, __shfl_xor_sync(0xFFFFFFFFu, mx, o));
        float se = expf(v0 - mx) + expf(v1 - mx) + expf(v2 - mx) + expf(v3 - mx);
#pragma unroll
        for (int o = 16; o > 0; o >>= 1) se += __shfl_xor_sync(0xFFFFFFFFu, se, o);
        float ls = mx + logf(se);
        size_t row = (size_t)(t0 + t) * IN_DIM;
        if (lane      < IN_DIM) out[row + lane]      = v0 - ls;
        if (lane + 32 < IN_DIM) out[row + lane + 32] = v1 - ls;
        if (lane + 64 < IN_DIM) out[row + lane + 64] = v2 - ls;
        if (lane + 96 < IN_DIM) out[row + lane + 96] = v3 - ls;
    }
}

// ---------------------------------------------------------------------------
// Fused kernel B: blocks 0..127 = layer-1 recurrence. Blocks 128..1151 = gated
// FC+log_softmax tiles (h1 rows t0..t0+7 visible once ctr1 >= 128*(t0+9)).
// ---------------------------------------------------------------------------
__global__ __launch_bounds__(256, 1) void fused_l1_fc(
    const float* __restrict__ Whh1,
    const float* __restrict__ xproj,
    float* __restrict__ h1,
    float* hbuf, unsigned* ctr,
    const float* __restrict__ fc_w, const float* __restrict__ fc_b,
    float* __restrict__ out)
{
    if (blockIdx.x < NBLK) {
        lstm_body(Whh1, xproj, h1, hbuf, ctr);
    } else {
        const int t0 = (blockIdx.x - NBLK) * 8;
        const unsigned target = (unsigned)NBLK * (unsigned)(t0 + 9);
        if (threadIdx.x == 0) {
            while (ld_acq_u(ctr) < target) { __nanosleep(1024); }
        }
        __syncthreads();
        fc_body(h1, fc_w, fc_b, out, t0);
    }
}

// ---------------------------------------------------------------------------
// Launch
// ---------------------------------------------------------------------------
extern "C" void kernel_launch(void* const* d_in, const int* in_sizes, int n_in,
                              void* d_out, int out_size)
{
    const float* input  = (const float*)d_in[0];   // [8192,109]
    const float* W_ih0  = (const float*)d_in[1];   // [4096,109]
    const float* W_hh0  = (const float*)d_in[2];   // [4096,1024]
    const float* b_ih0  = (const float*)d_in[3];
    const float* b_hh0  = (const float*)d_in[4];
    const float* W_ih1  = (const float*)d_in[5];   // [4096,1024]
    const float* W_hh1  = (const float*)d_in[6];   // [4096,1024]
    const float* b_ih1  = (const float*)d_in[7];
    const float* b_hh1  = (const float*)d_in[8];
    const float* fc_w   = (const float*)d_in[9];   // [109,1024]
    const float* fc_b   = (const float*)d_in[10];
    float* out = (float*)d_out;

    static float* p_xproj = nullptr;
    static float* p_h0 = nullptr;
    static float* p_h1 = nullptr;
    static float* p_hbuf = nullptr;
    static unsigned* p_ctr = nullptr;
    if (!p_xproj) {
        cudaGetSymbolAddress((void**)&p_xproj, g_xproj);
        cudaGetSymbolAddress((void**)&p_h0,    g_h0);
        cudaGetSymbolAddress((void**)&p_h1,    g_h1);
        cudaGetSymbolAddress((void**)&p_hbuf,  g_hbuf);
        cudaGetSymbolAddress((void**)&p_ctr,   g_ctr);
    }

    // 1) reset counters + h ping-pong buffers
    init_kernel<<<17, 256>>>();

    // 2) x_proj0 = input @ W_ih0^T + b_ih0 + b_hh0  (K=109)
    {
        dim3 grid(G_DIM / 128, T_STEPS / 128);
        gemm_nt_bias<<<grid, 256>>>(input, W_ih0, b_ih0, b_hh0,
                                    p_xproj, G_DIM, IN_DIM);
    }

    // 3) layer-0 recurrence + gated GEMM1 (xproj1) overlapped
    fused_l0_gemm1<<<NBLK + 2048, 256>>>(W_hh0, p_xproj, p_h0,
                                         p_hbuf + 0, p_ctr + 0,
                                         W_ih1, b_ih1, b_hh1);

    // 4) layer-1 recurrence + gated FC/log_softmax overlapped
    fused_l1_fc<<<NBLK + T_STEPS / 8, 256>>>(W_hh1, p_xproj, p_h1,
                                             p_hbuf + 2 * H_DIM, p_ctr + 32,
                                             fc_w, fc_b, out);
}

// round 12
// speedup vs baseline: 1.8888x; 1.0237x over previous
#include <cuda_runtime.h>
#include <cstdint>
#include <math.h>

// ---------------------------------------------------------------------------
// Problem dims
// ---------------------------------------------------------------------------
#define T_STEPS 8192
#define IN_DIM  109
#define H_DIM   1024
#define G_DIM   4096   // 4*H
#define NBLK    128    // persistent blocks (<=148 SMs, 1 CTA/SM -> co-resident)

// ---------------------------------------------------------------------------
// Scratch (static device allocations; no cudaMalloc allowed)
// ---------------------------------------------------------------------------
__device__ float g_xproj[(size_t)T_STEPS * G_DIM];   // reused for both layers
__device__ float g_h0[(size_t)T_STEPS * H_DIM];
__device__ float g_h1[(size_t)T_STEPS * H_DIM];
__device__ float g_hbuf[2][2 * H_DIM];               // [layer][parity*1024 + j]
// Cumulative step counters, one per layer, on separate 128B lines.
// Block adds 1 after each step (and one final bump): ctr == 128*t  <=>  all
// blocks completed step t-1. Max value 128*(T_STEPS+1).
__device__ unsigned g_ctr[64];                       // [0] layer0, [32] layer1

// ---------------------------------------------------------------------------
// Memory-order helpers
// ---------------------------------------------------------------------------
__device__ __forceinline__ unsigned ld_acq_u(const unsigned* p) {
    unsigned v;
    asm volatile("ld.acquire.gpu.b32 %0, [%1];" : "=r"(v) : "l"(p) : "memory");
    return v;
}
__device__ __forceinline__ void red_add_release(unsigned* p, unsigned v) {
    asm volatile("red.release.gpu.global.add.u32 [%0], %1;" :: "l"(p), "r"(v) : "memory");
}
__device__ __forceinline__ float4 ld_cv4(const float4* p) {
    float4 v;
    asm volatile("ld.global.cv.v4.f32 {%0,%1,%2,%3}, [%4];"
                 : "=f"(v.x), "=f"(v.y), "=f"(v.z), "=f"(v.w) : "l"(p) : "memory");
    return v;
}
__device__ __forceinline__ void st_cg(float* p, float v) {
    asm volatile("st.global.cg.f32 [%0], %1;" :: "l"(p), "f"(v) : "memory");
}

// ---- packed f32x2 (sm_100+) -----------------------------------------------
__device__ __forceinline__ unsigned long long pack2(float lo, float hi) {
    unsigned long long r;
    asm("mov.b64 %0, {%1, %2};" : "=l"(r) : "f"(lo), "f"(hi));
    return r;
}
__device__ __forceinline__ unsigned long long ffma2(
    unsigned long long a, unsigned long long b, unsigned long long c) {
    unsigned long long d;
    asm("fma.rn.f32x2 %0, %1, %2, %3;" : "=l"(d) : "l"(a), "l"(b), "l"(c));
    return d;
}
__device__ __forceinline__ void unpack2(unsigned long long v, float& lo, float& hi) {
    asm("mov.b64 {%0, %1}, %2;" : "=f"(lo), "=f"(hi) : "l"(v));
}

// ---- fast-accurate activations (abs err ~1e-6) ----------------------------
__device__ __forceinline__ float sig_fast(float x) {
    return __fdividef(1.0f, 1.0f + __expf(-x));
}

// ---------------------------------------------------------------------------
// Init: zero counters + hbuf (every launch; graph replays reuse statics)
// ---------------------------------------------------------------------------
__global__ void init_kernel() {
    int i = blockIdx.x * blockDim.x + threadIdx.x;
    if (i < 64) g_ctr[i] = 0u;
    if (i < 2 * 2 * H_DIM) ((float*)g_hbuf)[i] = 0.0f;
}

// ---------------------------------------------------------------------------
// GEMM tile body: C[m0..+128][n0..+128] = A@B^T + bias1 + bias2 (R1-proven)
// ---------------------------------------------------------------------------
__device__ void gemm_tile_body(
    const float* A, const float* B,
    const float* bias1, const float* bias2,
    float* C, int N, int K, int m0, int n0)
{
    __shared__ float As[8][132];
    __shared__ float Bs[8][132];

    const int tid = threadIdx.x;
    const int lr  = tid >> 1;
    const int lk4 = (tid & 1) * 4;
    const int ty  = tid >> 4;
    const int tx  = tid & 15;

    float acc[8][8];
#pragma unroll
    for (int i = 0; i < 8; i++)
#pragma unroll
        for (int j = 0; j < 8; j++) acc[i][j] = 0.0f;

    for (int k0 = 0; k0 < K; k0 += 8) {
#pragma unroll
        for (int e = 0; e < 4; e++) {
            int k = k0 + lk4 + e;
            float av = 0.0f, bv = 0.0f;
            if (k < K) {
                av = A[(size_t)(m0 + lr) * K + k];
                bv = B[(size_t)(n0 + lr) * K + k];
            }
            As[lk4 + e][lr] = av;
            Bs[lk4 + e][lr] = bv;
        }
        __syncthreads();
#pragma unroll
        for (int kk = 0; kk < 8; kk++) {
            float a[8], b[8];
            float4 a0 = *(const float4*)&As[kk][ty * 8];
            float4 a1 = *(const float4*)&As[kk][ty * 8 + 4];
            float4 b0 = *(const float4*)&Bs[kk][tx * 8];
            float4 b1 = *(const float4*)&Bs[kk][tx * 8 + 4];
            a[0]=a0.x; a[1]=a0.y; a[2]=a0.z; a[3]=a0.w;
            a[4]=a1.x; a[5]=a1.y; a[6]=a1.z; a[7]=a1.w;
            b[0]=b0.x; b[1]=b0.y; b[2]=b0.z; b[3]=b0.w;
            b[4]=b1.x; b[5]=b1.y; b[6]=b1.z; b[7]=b1.w;
#pragma unroll
            for (int i = 0; i < 8; i++)
#pragma unroll
                for (int j = 0; j < 8; j++)
                    acc[i][j] = fmaf(a[i], b[j], acc[i][j]);
        }
        __syncthreads();
    }

#pragma unroll
    for (int i = 0; i < 8; i++) {
        size_t row = (size_t)(m0 + ty * 8 + i) * N;
#pragma unroll
        for (int j = 0; j < 8; j++) {
            int n = n0 + tx * 8 + j;
            C[row + n] = acc[i][j] + bias1[n] + bias2[n];
        }
    }
}

// Standalone GEMM (x_proj0, K=109)
__global__ __launch_bounds__(256) void gemm_nt_bias(
    const float* __restrict__ A, const float* __restrict__ B,
    const float* __restrict__ bias1, const float* __restrict__ bias2,
    float* __restrict__ C, int N, int K)
{
    gemm_tile_body(A, B, bias1, bias2, C, N, K, blockIdx.y * 128, blockIdx.x * 128);
}

// ---------------------------------------------------------------------------
// LSTM recurrence body — R9/R10-proven protocol (single cumulative counter,
// 1 poller/block, release-RED arrive, final bump). NEW this round:
//  * mat-vec via packed fma.rn.f32x2 on row-pairs: per-row accumulation
//    chains identical (bit-exact trajectory), half the FMA instructions.
//  * activations via uniform sigmoid built on __expf (tanh = 2*sig(2x)-1):
//    abs err ~1e-6/step, strongly contracted by the recurrence.
// ---------------------------------------------------------------------------
__device__ void lstm_body(
    const float* __restrict__ Whh,   // [4096][1024]
    const float* xp,                 // [8192][4096] (may alias GEMM output)
    float* h_all,                    // [8192][1024]
    float* hbuf,                     // [2*1024]
    unsigned* ctr)
{
    const int b   = blockIdx.x;
    const int tid = threadIdx.x;
    const int rg  = tid >> 6;        // gate 0..3 (i,f,g,o)
    const int cg  = tid & 63;        // 0..63
    const int lane = tid & 31;
    const int warp = tid >> 5;
    const int half = warp & 1;

    __shared__ float4 hs4[256];
    __shared__ float  red[4][2][8];
    __shared__ float  actbuf[32];

    // Weights, packed as row-pairs: w2[p][c] = (row 2p, row 2p+1) at col c.
    // Rows are rg*1024 + b*8 + i, cols cg*4 + q*256 + e (same as before).
    unsigned long long w2[4][16];
#pragma unroll
    for (int p = 0; p < 4; p++) {
        const float* wr0 = Whh + (size_t)(rg * 1024 + b * 8 + 2 * p) * 1024 + cg * 4;
        const float* wr1 = wr0 + 1024;
#pragma unroll
        for (int q = 0; q < 4; q++) {
            float4 a = *(const float4*)(wr0 + q * 256);
            float4 c = *(const float4*)(wr1 + q * 256);
            w2[p][q * 4 + 0] = pack2(a.x, c.x);
            w2[p][q * 4 + 1] = pack2(a.y, c.y);
            w2[p][q * 4 + 2] = pack2(a.z, c.z);
            w2[p][q * 4 + 3] = pack2(a.w, c.w);
        }
    }

    float c_state = 0.0f;   // meaningful for tid < 8

    for (int t = 0; t < T_STEPS; ++t) {
        // x_proj prefetch: warp 0, lane (4*jj+g) -> gate g of element jj.
        float xv = 0.0f;
        if (tid < 32)
            xv = __ldcs(xp + (size_t)t * G_DIM + (tid & 3) * H_DIM + b * 8 + (tid >> 2));

        // Barrier: ctr >= 128*t  <=>  all blocks completed step t-1.
        if (t > 0) {
            if (tid == 0) {
                const unsigned target = (unsigned)NBLK * (unsigned)t;
                while (ld_acq_u(ctr) < target) { }
            }
            __syncthreads();
        }

        // Stage h[t-1] (L1-bypassing; the acquire above orders these reads).
        {
            const float4* hsrc = (const float4*)(hbuf + ((t + 1) & 1) * H_DIM);
            hs4[tid] = (t > 0) ? ld_cv4(hsrc + tid)
                               : make_float4(0.f, 0.f, 0.f, 0.f);
        }
        __syncthreads();

        // Mat-vec: 4 row-pairs x 16 cols per thread via FFMA2.
        // Column visit order (q, then x,y,z,w) identical to the scalar
        // version -> each row's chain is bit-identical.
        unsigned long long acc2[4];
#pragma unroll
        for (int p = 0; p < 4; p++) acc2[p] = 0ull;   // (0.0f, 0.0f)
#pragma unroll
        for (int q = 0; q < 4; q++) {
            float4 hv = hs4[cg + q * 64];
            unsigned long long hx = pack2(hv.x, hv.x);
            unsigned long long hy = pack2(hv.y, hv.y);
            unsigned long long hz = pack2(hv.z, hv.z);
            unsigned long long hw = pack2(hv.w, hv.w);
#pragma unroll
            for (int p = 0; p < 4; p++) {
                acc2[p] = ffma2(w2[p][q * 4 + 0], hx, acc2[p]);
                acc2[p] = ffma2(w2[p][q * 4 + 1], hy, acc2[p]);
                acc2[p] = ffma2(w2[p][q * 4 + 2], hz, acc2[p]);
                acc2[p] = ffma2(w2[p][q * 4 + 3], hw, acc2[p]);
            }
        }
        float acc[8];
#pragma unroll
        for (int p = 0; p < 4; p++) unpack2(acc2[p], acc[2 * p], acc[2 * p + 1]);

        // Butterfly reduce (unchanged order).
#pragma unroll
        for (int i = 0; i < 8; i++) {
#pragma unroll
            for (int off = 16; off > 0; off >>= 1)
                acc[i] += __shfl_xor_sync(0xFFFFFFFFu, acc[i], off);
        }
        if (lane == 0) {
#pragma unroll
            for (int i = 0; i < 8; i++) red[rg][half][i] = acc[i];
        }
        __syncthreads();

        // Tail: warp 0 computes 32 activations in parallel with a UNIFORM
        // sigmoid call (tanh(x) = 2*sig(2x)-1); threads 0..7 combine.
        if (tid < 32) {
            const int jj = tid >> 2;
            const int g  = tid & 3;
            float pre = red[g][0][jj] + red[g][1][jj] + xv;
            float arg = (g == 2) ? (pre + pre) : pre;
            float s   = sig_fast(arg);
            actbuf[tid] = (g == 2) ? fmaf(2.0f, s, -1.0f) : s;
            __syncwarp(0xFFFFFFFFu);

            if (tid < 8) {
                float ig = actbuf[tid * 4 + 0];
                float fg = actbuf[tid * 4 + 1];
                float gg = actbuf[tid * 4 + 2];
                float og = actbuf[tid * 4 + 3];
                c_state = fg * c_state + ig * gg;
                float s2 = sig_fast(c_state + c_state);     // tanh(c) = 2*sig(2c)-1
                float h  = og * fmaf(2.0f, s2, -1.0f);
                hbuf[(t & 1) * H_DIM + b * 8 + tid] = h;
                __syncwarp(0x000000FFu);
                if (tid == 0) {
                    red_add_release(ctr, 1u);      // release-arrive (hbuf visible)
                }
                __syncwarp(0x000000FFu);
                st_cg(h_all + (size_t)t * H_DIM + b * 8 + tid, h);
            }
        }
    }

    // Final bump: arrival T+1 publishes the last h_all rows to gated CTAs.
    __syncthreads();
    if (tid == 0) {
        red_add_release(ctr, 1u);
    }
}

// ---------------------------------------------------------------------------
// Fused kernel A: blocks 0..127 = layer-0 recurrence. Blocks 128.. = gated
// GEMM1 tiles (xproj1 = h0 @ W_ih1^T + biases) into g_xproj.
// Gate ctr0 >= 128*(m0+129): (a) h0 rows <= m0+127 visible; (b) xproj0 rows
// <= m0+128 consumed -> WAR-safe. One poller per tile CTA + backoff.
// ---------------------------------------------------------------------------
__global__ __launch_bounds__(256, 1) void fused_l0_gemm1(
    const float* __restrict__ Whh0,
    float* xproj,
    float* __restrict__ h0,
    float* hbuf, unsigned* ctr,
    const float* __restrict__ Wih1,
    const float* __restrict__ b_ih1, const float* __restrict__ b_hh1)
{
    if (blockIdx.x < NBLK) {
        lstm_body(Whh0, xproj, h0, hbuf, ctr);
    } else {
        const int tile = blockIdx.x - NBLK;       // 0..2047
        const int n0 = (tile & 31) * 128;         // G_DIM/128 = 32
        const int m0 = (tile >> 5) * 128;         // T_STEPS/128 = 64
        const unsigned target = (unsigned)NBLK * (unsigned)(m0 + 129);
        if (threadIdx.x == 0) {
            while (ld_acq_u(ctr) < target) { __nanosleep(1024); }
        }
        __syncthreads();
        gemm_tile_body(h0, Wih1, b_ih1, b_hh1, xproj, G_DIM, H_DIM, m0, n0);
    }
}

// ---------------------------------------------------------------------------
// FC (109 outputs) + log_softmax body. 8 timesteps per block.
// ---------------------------------------------------------------------------
__device__ void fc_body(
    const float* __restrict__ H, const float* __restrict__ Wf,
    const float* __restrict__ bf, float* __restrict__ out, int t0)
{
    __shared__ float ws[IN_DIM][68];
    __shared__ float hsm[8][68];
    __shared__ float lg[8][112];

    const int tid = threadIdx.x;
    const int tt  = tid & 7;
    const int n4  = tid >> 3;

    float acc[4] = {0.f, 0.f, 0.f, 0.f};

    for (int kc = 0; kc < H_DIM; kc += 64) {
        for (int idx = tid; idx < IN_DIM * 16; idx += 256) {
            int n = idx >> 4, k4 = idx & 15;
            *(float4*)&ws[n][k4 * 4] = *(const float4*)&Wf[(size_t)n * H_DIM + kc + k4 * 4];
        }
        for (int idx = tid; idx < 8 * 16; idx += 256) {
            int r = idx >> 4, k4 = idx & 15;
            *(float4*)&hsm[r][k4 * 4] = *(const float4*)&H[(size_t)(t0 + r) * H_DIM + kc + k4 * 4];
        }
        __syncthreads();
#pragma unroll
        for (int k4 = 0; k4 < 16; k4++) {
            float4 hv = *(const float4*)&hsm[tt][k4 * 4];
#pragma unroll
            for (int i = 0; i < 4; i++) {
                int n = n4 + i * 32;
                if (n < IN_DIM) {
                    float4 wv = *(const float4*)&ws[n][k4 * 4];
                    acc[i] += hv.x * wv.x + hv.y * wv.y + hv.z * wv.z + hv.w * wv.w;
                }
            }
        }
        __syncthreads();
    }

#pragma unroll
    for (int i = 0; i < 4; i++) {
        int n = n4 + i * 32;
        if (n < IN_DIM) lg[tt][n] = acc[i] + bf[n];
    }
    __syncthreads();

    const int wp = tid >> 5, lane = tid & 31;
    {
        int t = wp;
        float v0 = (lane       < IN_DIM) ? lg[t][lane]       : -INFINITY;
        float v1 = (lane + 32  < IN_DIM) ? lg[t][lane + 32]  : -INFINITY;
        float v2 = (lane + 64  < IN_DIM) ? lg[t][lane + 64]  : -INFINITY;
        float v3 = (lane + 96  < IN_DIM) ? lg[t][lane + 96]  : -INFINITY;
        float mx = fmaxf(fmaxf(v0, v1), fmaxf(v2, v3));
#pragma unroll
        for (int o = 16; o > 0; o >>= 1) mx = fmaxf(mx, __shfl_xor_sync(0xFFFFFFFFu, mx, o));
        float se = expf(v0 - mx) + expf(v1 - mx) + expf(v2 - mx) + expf(v3 - mx);
#pragma unroll
        for (int o = 16; o > 0; o >>= 1) se += __shfl_xor_sync(0xFFFFFFFFu, se, o);
        float ls = mx + logf(se);
        size_t row = (size_t)(t0 + t) * IN_DIM;
        if (lane      < IN_DIM) out[row + lane]      = v0 - ls;
        if (lane + 32 < IN_DIM) out[row + lane + 32] = v1 - ls;
        if (lane + 64 < IN_DIM) out[row + lane + 64] = v2 - ls;
        if (lane + 96 < IN_DIM) out[row + lane + 96] = v3 - ls;
    }
}

// ---------------------------------------------------------------------------
// Fused kernel B: blocks 0..127 = layer-1 recurrence. Blocks 128..1151 = gated
// FC+log_softmax tiles (h1 rows t0..t0+7 visible once ctr1 >= 128*(t0+9)).
// ---------------------------------------------------------------------------
__global__ __launch_bounds__(256, 1) void fused_l1_fc(
    const float* __restrict__ Whh1,
    const float* __restrict__ xproj,
    float* __restrict__ h1,
    float* hbuf, unsigned* ctr,
    const float* __restrict__ fc_w, const float* __restrict__ fc_b,
    float* __restrict__ out)
{
    if (blockIdx.x < NBLK) {
        lstm_body(Whh1, xproj, h1, hbuf, ctr);
    } else {
        const int t0 = (blockIdx.x - NBLK) * 8;
        const unsigned target = (unsigned)NBLK * (unsigned)(t0 + 9);
        if (threadIdx.x == 0) {
            while (ld_acq_u(ctr) < target) { __nanosleep(1024); }
        }
        __syncthreads();
        fc_body(h1, fc_w, fc_b, out, t0);
    }
}

// ---------------------------------------------------------------------------
// Launch
// ---------------------------------------------------------------------------
extern "C" void kernel_launch(void* const* d_in, const int* in_sizes, int n_in,
                              void* d_out, int out_size)
{
    const float* input  = (const float*)d_in[0];   // [8192,109]
    const float* W_ih0  = (const float*)d_in[1];   // [4096,109]
    const float* W_hh0  = (const float*)d_in[2];   // [4096,1024]
    const float* b_ih0  = (const float*)d_in[3];
    const float* b_hh0  = (const float*)d_in[4];
    const float* W_ih1  = (const float*)d_in[5];   // [4096,1024]
    const float* W_hh1  = (const float*)d_in[6];   // [4096,1024]
    const float* b_ih1  = (const float*)d_in[7];
    const float* b_hh1  = (const float*)d_in[8];
    const float* fc_w   = (const float*)d_in[9];   // [109,1024]
    const float* fc_b   = (const float*)d_in[10];
    float* out = (float*)d_out;

    static float* p_xproj = nullptr;
    static float* p_h0 = nullptr;
    static float* p_h1 = nullptr;
    static float* p_hbuf = nullptr;
    static unsigned* p_ctr = nullptr;
    if (!p_xproj) {
        cudaGetSymbolAddress((void**)&p_xproj, g_xproj);
        cudaGetSymbolAddress((void**)&p_h0,    g_h0);
        cudaGetSymbolAddress((void**)&p_h1,    g_h1);
        cudaGetSymbolAddress((void**)&p_hbuf,  g_hbuf);
        cudaGetSymbolAddress((void**)&p_ctr,   g_ctr);
    }

    // 1) reset counters + h ping-pong buffers
    init_kernel<<<17, 256>>>();

    // 2) x_proj0 = input @ W_ih0^T + b_ih0 + b_hh0  (K=109)
    {
        dim3 grid(G_DIM / 128, T_STEPS / 128);
        gemm_nt_bias<<<grid, 256>>>(input, W_ih0, b_ih0, b_hh0,
                                    p_xproj, G_DIM, IN_DIM);
    }

    // 3) layer-0 recurrence + gated GEMM1 (xproj1) overlapped
    fused_l0_gemm1<<<NBLK + 2048, 256>>>(W_hh0, p_xproj, p_h0,
                                         p_hbuf + 0, p_ctr + 0,
                                         W_ih1, b_ih1, b_hh1);

    // 4) layer-1 recurrence + gated FC/log_softmax overlapped
    fused_l1_fc<<<NBLK + T_STEPS / 8, 256>>>(W_hh1, p_xproj, p_h1,
                                             p_hbuf + 2 * H_DIM, p_ctr + 32,
                                             fc_w, fc_b, out);
}